// round 4
// baseline (speedup 1.0000x reference)
#include <cuda_runtime.h>
#include <cuda_bf16.h>
#include <math.h>

// ---------------- problem constants ----------------
#define LAYERS 2
#define D      1024
#define H      16
#define DH     64
#define FF     4096
#define NE     8
#define TOPK   2
#define V      32000
#define IH     4
#define ID     64
#define IHD    256
#define B      2
#define S      1024
#define NT     2048
#define KSEL   512
#define NEGV   (-1e9f)
#define EPS    1e-5f

// ---------------- scratch ----------------
#define M2 2097152UL
__device__ float g_buf[48UL * M2];

#define OFF_H   (0UL)
#define OFF_HN  (1UL * M2)
#define OFF_Q   (2UL * M2)
#define OFF_K   (3UL * M2)
#define OFF_V   (4UL * M2)
#define OFF_ATT (5UL * M2)
#define OFF_QI  (6UL * M2)
#define OFF_KI  (6UL * M2 + 524288UL)
#define OFF_IS  (7UL * M2)
#define OFF_Y   (8UL * M2)
#define OFF_HID (16UL * M2)

__device__ unsigned g_selmask[NT * 32];
__device__ int      g_elist[NE * NT];
__device__ int      g_ecount[NE];
__device__ int      g_tope[NT * 2];
__device__ float    g_gate[NT * 2];
__device__ int      g_slot[NT * 2];

// ---------------- helpers ----------------
__device__ __forceinline__ float gelu_f(float x) {
    const float c = 0.7978845608028654f;
    float x3 = x * x * x;
    return 0.5f * x * (1.0f + tanhf(c * (x + 0.044715f * x3)));
}

__device__ __forceinline__ void split3(float a, float& h, float& m, float& l) {
    unsigned hb; asm("cvt.rna.tf32.f32 %0, %1;" : "=r"(hb) : "f"(a));
    h = __uint_as_float(hb);
    float r1 = a - h;
    unsigned mb; asm("cvt.rna.tf32.f32 %0, %1;" : "=r"(mb) : "f"(r1));
    m = __uint_as_float(mb);
    float r2 = r1 - m;
    unsigned lb; asm("cvt.rna.tf32.f32 %0, %1;" : "=r"(lb) : "f"(r2));
    l = __uint_as_float(lb);
}

// ---------------- embedding ----------------
__global__ void embed_kernel(const int* __restrict__ ids,
                             const float* __restrict__ tok_emb,
                             const float* __restrict__ pos_emb,
                             float* __restrict__ h) {
    long idx = (long)blockIdx.x * blockDim.x + threadIdx.x;
    if (idx >= (long)NT * D) return;
    int tok = (int)(idx / D);
    int d   = (int)(idx % D);
    int s   = tok % S;
    h[idx] = tok_emb[(long)ids[tok] * D + d] + pos_emb[(long)s * D + d];
}

// ---------------- layernorm ----------------
__global__ void ln_kernel(const float* __restrict__ x,
                          const float* __restrict__ g,
                          const float* __restrict__ b,
                          float* __restrict__ y) {
    int row = blockIdx.x;
    int t = threadIdx.x;
    __shared__ float red[256];
    __shared__ float s_mean, s_inv;
    const float* xr = x + (long)row * D;
    float s = 0.f;
    for (int i = t; i < D; i += 256) s += xr[i];
    red[t] = s; __syncthreads();
    for (int o = 128; o > 0; o >>= 1) { if (t < o) red[t] += red[t + o]; __syncthreads(); }
    if (t == 0) s_mean = red[0] / (float)D;
    __syncthreads();
    float m = s_mean;
    float s2 = 0.f;
    for (int i = t; i < D; i += 256) { float d = xr[i] - m; s2 += d * d; }
    red[t] = s2; __syncthreads();
    for (int o = 128; o > 0; o >>= 1) { if (t < o) red[t] += red[t + o]; __syncthreads(); }
    if (t == 0) s_inv = rsqrtf(red[0] / (float)D + EPS);
    __syncthreads();
    float inv = s_inv;
    float* yr = y + (long)row * D;
    for (int i = t; i < D; i += 256) yr[i] = (xr[i] - m) * inv * g[i] + b[i];
}

// ---------------- multi-term TF32 tensor-core GEMM ----------------
// C[N,M] = act(A[N,K] @ W[K,M] + bias) (+resid). fp32 in/out.
// 3-way tf32 split; TERMS=6 -> error ~2^-32/product, TERMS=3 -> ~2^-22.
// 128x128 tile, BK=16, 8 warps (2x4), warp tile 64x32, double-buffered smem.
#define GRS 136
#define GBUF (6 * 16 * GRS)            // 6 planes (Ah,Am,Al,Bh,Bm,Bl)
#define GEMM_SMEM (2 * GBUF * 4)

#define MMA_TF32(c, a, b) \
  asm volatile("mma.sync.aligned.m16n8k8.row.col.f32.tf32.tf32.f32 " \
      "{%0,%1,%2,%3}, {%4,%5,%6,%7}, {%8,%9}, {%0,%1,%2,%3};" \
      : "+f"((c)[0]), "+f"((c)[1]), "+f"((c)[2]), "+f"((c)[3]) \
      : "r"((a)[0]), "r"((a)[1]), "r"((a)[2]), "r"((a)[3]), \
        "r"((b)[0]), "r"((b)[1]))

template<int TERMS>
__global__ __launch_bounds__(256)
void gemm_split_kernel(const float* __restrict__ A, const float* __restrict__ W,
                       const float* __restrict__ bias, const float* __restrict__ resid,
                       float* __restrict__ C, int N, int M, int K,
                       const int* __restrict__ row_idx, const int* __restrict__ n_ptr,
                       int act) {
    extern __shared__ float smdyn[];
    int n = n_ptr ? *n_ptr : N;
    int br = blockIdx.y * 128;
    int bc = blockIdx.x * 128;
    if (br >= n) return;

    int t = threadIdx.x;
    int warp = t >> 5, lane = t & 31;
    int wm = (warp >> 2) * 64;
    int wn = (warp & 3) * 32;
    int g = lane >> 2, kt = lane & 3;

    int ar0 = t >> 2,         ak0 = (t & 3) * 4;
    int ar1 = (t + 256) >> 2;
    int bk0 = t >> 5,         bn0 = (t & 31) * 4;
    int bk1 = bk0 + 8;

    long arow0, arow1;
    {
        int gr0 = br + ar0, gr1 = br + ar1;
        arow0 = (gr0 < n) ? (row_idx ? (long)row_idx[gr0] : (long)gr0) : 0;
        arow1 = (gr1 < n) ? (row_idx ? (long)row_idx[gr1] : (long)gr1) : 0;
    }

    float acc[4][4][4];
#pragma unroll
    for (int i = 0; i < 4; i++)
#pragma unroll
        for (int j = 0; j < 4; j++)
#pragma unroll
            for (int c = 0; c < 4; c++) acc[i][j][c] = 0.f;

    float4 aR0, aR1, bR0, bR1;

    auto loadG = [&](int k0) {
        aR0 = *(const float4*)(A + arow0 * K + k0 + ak0);
        aR1 = *(const float4*)(A + arow1 * K + k0 + ak0);
        bR0 = *(const float4*)(W + (long)(k0 + bk0) * M + bc + bn0);
        bR1 = *(const float4*)(W + (long)(k0 + bk1) * M + bc + bn0);
    };

    auto storeS = [&](int bufi) {
        float* base = smdyn + bufi * GBUF;
        float* Ah = base;
        float* Am = base + 16 * GRS;
        float* Al = base + 32 * GRS;
        float* Bh = base + 48 * GRS;
        float* Bm = base + 64 * GRS;
        float* Bl = base + 80 * GRS;
        float av0[4] = {aR0.x, aR0.y, aR0.z, aR0.w};
        float av1[4] = {aR1.x, aR1.y, aR1.z, aR1.w};
#pragma unroll
        for (int j = 0; j < 4; j++) {
            float hv, mv, lv;
            split3(av0[j], hv, mv, lv);
            int o = (ak0 + j) * GRS + ar0;
            Ah[o] = hv; Am[o] = mv; Al[o] = lv;
            split3(av1[j], hv, mv, lv);
            o = (ak0 + j) * GRS + ar1;
            Ah[o] = hv; Am[o] = mv; Al[o] = lv;
        }
        float bv0[4] = {bR0.x, bR0.y, bR0.z, bR0.w};
        float bv1[4] = {bR1.x, bR1.y, bR1.z, bR1.w};
        float4 h0, m0v, l0, h1, m1v, l1;
        float *ph0 = (float*)&h0, *pm0 = (float*)&m0v, *pl0 = (float*)&l0;
        float *ph1 = (float*)&h1, *pm1 = (float*)&m1v, *pl1 = (float*)&l1;
#pragma unroll
        for (int j = 0; j < 4; j++) {
            split3(bv0[j], ph0[j], pm0[j], pl0[j]);
            split3(bv1[j], ph1[j], pm1[j], pl1[j]);
        }
        *(float4*)&Bh[bk0 * GRS + bn0] = h0;
        *(float4*)&Bm[bk0 * GRS + bn0] = m0v;
        *(float4*)&Bl[bk0 * GRS + bn0] = l0;
        *(float4*)&Bh[bk1 * GRS + bn0] = h1;
        *(float4*)&Bm[bk1 * GRS + bn0] = m1v;
        *(float4*)&Bl[bk1 * GRS + bn0] = l1;
    };

    auto compute = [&](int bufi) {
        const float* base = smdyn + bufi * GBUF;
        const float* Ah = base;
        const float* Am = base + 16 * GRS;
        const float* Al = base + 32 * GRS;
        const float* Bh = base + 48 * GRS;
        const float* Bm = base + 64 * GRS;
        const float* Bl = base + 80 * GRS;
#pragma unroll
        for (int ks = 0; ks < 2; ks++) {
            int kb = ks * 8;
            unsigned bh[4][2], bm[4][2], bl[4][2];
#pragma unroll
            for (int nt = 0; nt < 4; nt++) {
                int c0 = wn + nt * 8 + g;
                int o0 = (kb + kt) * GRS + c0;
                int o1 = (kb + kt + 4) * GRS + c0;
                bh[nt][0] = __float_as_uint(Bh[o0]);
                bh[nt][1] = __float_as_uint(Bh[o1]);
                bm[nt][0] = __float_as_uint(Bm[o0]);
                bm[nt][1] = __float_as_uint(Bm[o1]);
                if (TERMS == 6) {
                    bl[nt][0] = __float_as_uint(Bl[o0]);
                    bl[nt][1] = __float_as_uint(Bl[o1]);
                }
            }
#pragma unroll
            for (int mt = 0; mt < 4; mt++) {
                int m0 = wm + mt * 16 + g;
                int o0 = (kb + kt) * GRS + m0;
                int o1 = (kb + kt + 4) * GRS + m0;
                unsigned ah[4] = {__float_as_uint(Ah[o0]), __float_as_uint(Ah[o0 + 8]),
                                  __float_as_uint(Ah[o1]), __float_as_uint(Ah[o1 + 8])};
                unsigned am[4] = {__float_as_uint(Am[o0]), __float_as_uint(Am[o0 + 8]),
                                  __float_as_uint(Am[o1]), __float_as_uint(Am[o1 + 8])};
                unsigned al[4] = {0u, 0u, 0u, 0u};
                if (TERMS == 6) {
                    al[0] = __float_as_uint(Al[o0]); al[1] = __float_as_uint(Al[o0 + 8]);
                    al[2] = __float_as_uint(Al[o1]); al[3] = __float_as_uint(Al[o1 + 8]);
                }
#pragma unroll
                for (int nt = 0; nt < 4; nt++) {
                    MMA_TF32(acc[mt][nt], ah, bh[nt]);
                    MMA_TF32(acc[mt][nt], am, bh[nt]);
                    MMA_TF32(acc[mt][nt], ah, bm[nt]);
                    if (TERMS == 6) {
                        MMA_TF32(acc[mt][nt], am, bm[nt]);
                        MMA_TF32(acc[mt][nt], al, bh[nt]);
                        MMA_TF32(acc[mt][nt], ah, bl[nt]);
                    }
                }
            }
        }
    };

    int NI = K / 16;
    loadG(0);
    storeS(0);
    __syncthreads();
    for (int it = 0; it < NI; it++) {
        if (it + 1 < NI) loadG((it + 1) * 16);
        compute(it & 1);
        if (it + 1 < NI) storeS((it + 1) & 1);
        __syncthreads();
    }

#pragma unroll
    for (int mt = 0; mt < 4; mt++) {
        int r0 = br + wm + mt * 16 + g;
        int r1 = r0 + 8;
#pragma unroll
        for (int nt = 0; nt < 4; nt++) {
            int c = bc + wn + nt * 8 + kt * 2;
            float v00 = acc[mt][nt][0], v01 = acc[mt][nt][1];
            float v10 = acc[mt][nt][2], v11 = acc[mt][nt][3];
            if (bias) {
                float b0 = bias[c], b1 = bias[c + 1];
                v00 += b0; v01 += b1; v10 += b0; v11 += b1;
            }
            if (act == 1) {
                v00 = gelu_f(v00); v01 = gelu_f(v01);
                v10 = gelu_f(v10); v11 = gelu_f(v11);
            }
            if (r0 < n) {
                long o = (long)r0 * M + c;
                if (resid) { v00 += resid[o]; v01 += resid[o + 1]; }
                C[o] = v00; C[o + 1] = v01;
            }
            if (r1 < n) {
                long o = (long)r1 * M + c;
                if (resid) { v10 += resid[o]; v11 += resid[o + 1]; }
                C[o] = v10; C[o + 1] = v11;
            }
        }
    }
}

// ---------------- indexer scores ----------------
__global__ void idx_score_kernel(const float* __restrict__ qi,
                                 const float* __restrict__ ki,
                                 const float* __restrict__ hw,
                                 float* __restrict__ sc) {
    int row = blockIdx.x;
    int b = row / S;
    int t = threadIdx.x;
    __shared__ float qs[IHD];
    __shared__ float w[IH];
    if (t < IHD) qs[t] = qi[(long)row * IHD + t];
    if (t < IH) w[t] = hw[t];
    __syncthreads();
    for (int k = t; k < S; k += 256) {
        const float* kr = ki + (long)(b * S + k) * IHD;
        float s = 0.f;
#pragma unroll
        for (int hh = 0; hh < IH; hh++) {
            float d = 0.f;
#pragma unroll
            for (int i = 0; i < ID; i++) d += qs[hh * ID + i] * kr[hh * ID + i];
            s += w[hh] * fmaxf(d, 0.f);
        }
        sc[(long)row * S + k] = s;
    }
}

// ---------------- exact stable top-k (rank counting) ----------------
__global__ void topk_kernel(const float* __restrict__ sc, unsigned* __restrict__ sel) {
    int row = blockIdx.x;
    int t = threadIdx.x;
    __shared__ float s[S];
    s[t] = sc[(long)row * S + t];
    __syncthreads();
    float v = s[t];
    int cnt = 0;
    for (int i = 0; i < S; i++) {
        float si = s[i];
        cnt += (si > v) || (si == v && i < t);
    }
    unsigned ball = __ballot_sync(0xffffffffu, cnt < KSEL);
    if ((t & 31) == 0) sel[row * 32 + (t >> 5)] = ball;
}

// ---------------- fused attention ----------------
__global__ void attn_kernel(const float* __restrict__ q, const float* __restrict__ k,
                            const float* __restrict__ v, const unsigned* __restrict__ selmask,
                            float* __restrict__ out) {
    int idx = blockIdx.x;
    int qpos = idx % S;
    int hh = (idx / S) % H;
    int b = idx / (S * H);
    int t = threadIdx.x;

    __shared__ float qs[DH];
    __shared__ float sc[S];
    __shared__ float red[256];
    __shared__ float s_max, s_inv;

    const float* qrow = q + ((long)(b * S + qpos) * D + hh * DH);
    if (t < DH) qs[t] = qrow[t];
    __syncthreads();

    const unsigned* selrow = selmask + (long)(b * S + qpos) * 32;
    for (int kk = t; kk < S; kk += 256) {
        const float* krow = k + ((long)(b * S + kk) * D + hh * DH);
        float d = 0.f;
#pragma unroll
        for (int i = 0; i < DH; i++) d += qs[i] * krow[i];
        d *= 0.125f;
        bool allowed = (kk <= qpos) && ((selrow[kk >> 5] >> (kk & 31)) & 1u);
        sc[kk] = allowed ? d : (d + NEGV);
    }
    __syncthreads();

    float m = -INFINITY;
    for (int kk = t; kk < S; kk += 256) m = fmaxf(m, sc[kk]);
    red[t] = m; __syncthreads();
    for (int o = 128; o > 0; o >>= 1) { if (t < o) red[t] = fmaxf(red[t], red[t + o]); __syncthreads(); }
    if (t == 0) s_max = red[0];
    __syncthreads();
    float mx = s_max;

    float sum = 0.f;
    for (int kk = t; kk < S; kk += 256) {
        float p = expf(sc[kk] - mx);
        sc[kk] = p;
        sum += p;
    }
    red[t] = sum; __syncthreads();
    for (int o = 128; o > 0; o >>= 1) { if (t < o) red[t] += red[t + o]; __syncthreads(); }
    if (t == 0) s_inv = 1.f / red[0];
    __syncthreads();
    float inv = s_inv;

    int d = t & 63;
    int chunk = t >> 6;
    float acc = 0.f;
    int kbeg = chunk * 256, kend = kbeg + 256;
    for (int kk = kbeg; kk < kend; kk++)
        acc += sc[kk] * v[(long)(b * S + kk) * D + hh * DH + d];
    red[t] = acc; __syncthreads();
    if (t < 64) {
        float o = (red[t] + red[t + 64] + red[t + 128] + red[t + 192]) * inv;
        out[(long)(b * S + qpos) * D + hh * DH + t] = o;
    }
}

// ---------------- router ----------------
__global__ void router_kernel(const float* __restrict__ x, const float* __restrict__ w,
                              const float* __restrict__ bias,
                              int* __restrict__ tope, float* __restrict__ gate,
                              int* __restrict__ slot, int* __restrict__ elist,
                              int* __restrict__ ecount) {
    int tkn = blockIdx.x;
    int t = threadIdx.x;
    int e = t >> 5, lane = t & 31;
    __shared__ float logit[NE];
    const float* xr = x + (long)tkn * D;
    float s = 0.f;
    for (int i = lane; i < D; i += 32) s += xr[i] * w[(long)i * NE + e];
#pragma unroll
    for (int o = 16; o > 0; o >>= 1) s += __shfl_down_sync(0xffffffffu, s, o);
    if (lane == 0) logit[e] = s + bias[e];
    __syncthreads();
    if (t == 0) {
        float mx = logit[0];
        for (int i = 1; i < NE; i++) mx = fmaxf(mx, logit[i]);
        float p[NE]; float sum = 0.f;
        for (int i = 0; i < NE; i++) { p[i] = expf(logit[i] - mx); sum += p[i]; }
        float invs = 1.f / sum;
        for (int i = 0; i < NE; i++) p[i] *= invs;
        int i0 = 0;
        for (int i = 1; i < NE; i++) if (p[i] > p[i0]) i0 = i;
        int i1 = -1;
        for (int i = 0; i < NE; i++) { if (i == i0) continue; if (i1 < 0 || p[i] > p[i1]) i1 = i; }
        float g0 = p[i0], g1 = p[i1];
        float ginv = 1.f / (g0 + g1);
        g0 *= ginv; g1 *= ginv;
        tope[2 * tkn] = i0; tope[2 * tkn + 1] = i1;
        gate[2 * tkn] = g0; gate[2 * tkn + 1] = g1;
        int s0 = atomicAdd(&ecount[i0], 1); elist[i0 * NT + s0] = tkn; slot[2 * tkn] = s0;
        int s1 = atomicAdd(&ecount[i1], 1); elist[i1 * NT + s1] = tkn; slot[2 * tkn + 1] = s1;
    }
}

__global__ void zero_counts_kernel(int* __restrict__ ecount) {
    if (threadIdx.x < NE) ecount[threadIdx.x] = 0;
}

// ---------------- MoE gather ----------------
__global__ void moe_gather_kernel(const float* __restrict__ y, const int* __restrict__ tope,
                                  const float* __restrict__ gate, const int* __restrict__ slot,
                                  float* __restrict__ h) {
    long idx = (long)blockIdx.x * blockDim.x + threadIdx.x;
    if (idx >= (long)NT * D) return;
    int tkn = (int)(idx / D);
    int d = (int)(idx % D);
    int e0 = tope[2 * tkn], e1 = tope[2 * tkn + 1];
    float g0 = gate[2 * tkn], g1 = gate[2 * tkn + 1];
    long r0 = (long)(e0 * NT + slot[2 * tkn]) * D + d;
    long r1 = (long)(e1 * NT + slot[2 * tkn + 1]) * D + d;
    h[idx] += g0 * y[r0] + g1 * y[r1];
}

// ---------------- launch ----------------
static inline void launch_gemm6(const float* A, const float* W, const float* bias,
                                const float* resid, float* C, int N, int M, int K,
                                const int* row_idx, const int* n_ptr, int act) {
    dim3 grid((M + 127) / 128, (N + 127) / 128);
    gemm_split_kernel<6><<<grid, 256, GEMM_SMEM>>>(A, W, bias, resid, C, N, M, K, row_idx, n_ptr, act);
}
static inline void launch_gemm3(const float* A, const float* W, const float* bias,
                                const float* resid, float* C, int N, int M, int K,
                                const int* row_idx, const int* n_ptr, int act) {
    dim3 grid((M + 127) / 128, (N + 127) / 128);
    gemm_split_kernel<3><<<grid, 256, GEMM_SMEM>>>(A, W, bias, resid, C, N, M, K, row_idx, n_ptr, act);
}

extern "C" void kernel_launch(void* const* d_in, const int* in_sizes, int n_in,
                              void* d_out, int out_size) {
    const int*   input_ids = (const int*)d_in[0];
    const float* tok_emb   = (const float*)d_in[1];
    const float* pos_emb   = (const float*)d_in[2];
    const float* ind_qw    = (const float*)d_in[3];
    const float* ind_qb    = (const float*)d_in[4];
    const float* ind_kw    = (const float*)d_in[5];
    const float* ind_kb    = (const float*)d_in[6];
    const float* ind_hw    = (const float*)d_in[7];
    const float* an_g      = (const float*)d_in[8];
    const float* an_b      = (const float*)d_in[9];
    const float* q_w       = (const float*)d_in[10];
    const float* q_b       = (const float*)d_in[11];
    const float* k_w       = (const float*)d_in[12];
    const float* k_b       = (const float*)d_in[13];
    const float* v_w       = (const float*)d_in[14];
    const float* v_b       = (const float*)d_in[15];
    const float* o_w       = (const float*)d_in[16];
    const float* o_b       = (const float*)d_in[17];
    const float* mn_g      = (const float*)d_in[18];
    const float* mn_b      = (const float*)d_in[19];
    const float* router_w  = (const float*)d_in[20];
    const float* router_b  = (const float*)d_in[21];
    const float* e_w1      = (const float*)d_in[22];
    const float* e_b1      = (const float*)d_in[23];
    const float* e_w2      = (const float*)d_in[24];
    const float* e_b2      = (const float*)d_in[25];
    const float* ln_g      = (const float*)d_in[26];
    const float* ln_b      = (const float*)d_in[27];
    const float* out_w     = (const float*)d_in[28];
    const float* out_b     = (const float*)d_in[29];
    float* out = (float*)d_out;

    cudaFuncSetAttribute(gemm_split_kernel<6>, cudaFuncAttributeMaxDynamicSharedMemorySize, GEMM_SMEM);
    cudaFuncSetAttribute(gemm_split_kernel<3>, cudaFuncAttributeMaxDynamicSharedMemorySize, GEMM_SMEM);

    float* buf = nullptr;
    cudaGetSymbolAddress((void**)&buf, g_buf);
    unsigned* selmask = nullptr; cudaGetSymbolAddress((void**)&selmask, g_selmask);
    int* elist = nullptr;  cudaGetSymbolAddress((void**)&elist, g_elist);
    int* ecount = nullptr; cudaGetSymbolAddress((void**)&ecount, g_ecount);
    int* tope = nullptr;   cudaGetSymbolAddress((void**)&tope, g_tope);
    float* gate = nullptr; cudaGetSymbolAddress((void**)&gate, g_gate);
    int* slot = nullptr;   cudaGetSymbolAddress((void**)&slot, g_slot);

    float* h    = buf + OFF_H;
    float* hn   = buf + OFF_HN;
    float* qb   = buf + OFF_Q;
    float* kb   = buf + OFF_K;
    float* vb   = buf + OFF_V;
    float* attb = buf + OFF_ATT;
    float* qib  = buf + OFF_QI;
    float* kib  = buf + OFF_KI;
    float* isb  = buf + OFF_IS;
    float* yb   = buf + OFF_Y;
    float* hidb = buf + OFF_HID;

    embed_kernel<<<(NT * D + 255) / 256, 256>>>(input_ids, tok_emb, pos_emb, h);

    for (int l = 0; l < LAYERS; l++) {
        const float* iqw = ind_qw + (long)l * D * IHD;
        const float* iqb_ = ind_qb + (long)l * IHD;
        const float* ikw = ind_kw + (long)l * D * IHD;
        const float* ikb_ = ind_kb + (long)l * IHD;
        const float* ihw = ind_hw + (long)l * IH;

        launch_gemm6(h, iqw, iqb_, nullptr, qib, NT, IHD, D, nullptr, nullptr, 0);
        launch_gemm6(h, ikw, ikb_, nullptr, kib, NT, IHD, D, nullptr, nullptr, 0);
        idx_score_kernel<<<NT, 256>>>(qib, kib, ihw, isb);
        topk_kernel<<<NT, 1024>>>(isb, selmask);

        ln_kernel<<<NT, 256>>>(h, an_g + (long)l * D, an_b + (long)l * D, hn);
        launch_gemm6(hn, q_w + (long)l * D * D, q_b + (long)l * D, nullptr, qb, NT, D, D, nullptr, nullptr, 0);
        launch_gemm6(hn, k_w + (long)l * D * D, k_b + (long)l * D, nullptr, kb, NT, D, D, nullptr, nullptr, 0);
        launch_gemm6(hn, v_w + (long)l * D * D, v_b + (long)l * D, nullptr, vb, NT, D, D, nullptr, nullptr, 0);
        attn_kernel<<<B * H * S, 256>>>(qb, kb, vb, selmask, attb);
        launch_gemm6(attb, o_w + (long)l * D * D, o_b + (long)l * D, h, h, NT, D, D, nullptr, nullptr, 0);

        ln_kernel<<<NT, 256>>>(h, mn_g + (long)l * D, mn_b + (long)l * D, hn);
        zero_counts_kernel<<<1, 32>>>(ecount);
        router_kernel<<<NT, 256>>>(hn, router_w + (long)l * D * NE, router_b + (long)l * NE,
                                   tope, gate, slot, elist, ecount);
        for (int e = 0; e < NE; e++) {
            const float* w1 = e_w1 + ((long)l * NE + e) * (long)D * FF;
            const float* b1 = e_b1 + ((long)l * NE + e) * FF;
            launch_gemm6(hn, w1, b1, nullptr, hidb + (long)e * NT * FF, NT, FF, D,
                         elist + e * NT, ecount + e, 1);
        }
        for (int e = 0; e < NE; e++) {
            const float* w2 = e_w2 + ((long)l * NE + e) * (long)FF * D;
            const float* b2 = e_b2 + ((long)l * NE + e) * D;
            launch_gemm6(hidb + (long)e * NT * FF, w2, b2, nullptr, yb + (long)e * NT * D,
                         NT, D, FF, nullptr, ecount + e, 0);
        }
        moe_gather_kernel<<<(NT * D + 255) / 256, 256>>>(yb, tope, gate, slot, h);
    }

    ln_kernel<<<NT, 256>>>(h, ln_g, ln_b, hn);
    launch_gemm3(hn, out_w, out_b, nullptr, out, NT, V, D, nullptr, nullptr, 0);
}

// round 5
// speedup vs baseline: 1.2032x; 1.2032x over previous
#include <cuda_runtime.h>
#include <cuda_bf16.h>
#include <math.h>

// ---------------- problem constants ----------------
#define LAYERS 2
#define D      1024
#define H      16
#define DH     64
#define FF     4096
#define NE     8
#define V      32000
#define IH     4
#define ID     64
#define IHD    256
#define B      2
#define S      1024
#define NT     2048
#define KSEL   512
#define NEGV   (-1e9f)
#define EPS    1e-5f

// ---------------- scratch ----------------
#define M2 2097152UL
__device__ float g_buf[48UL * M2];

#define OFF_H   (0UL)
#define OFF_HN  (1UL * M2)
#define OFF_Q   (2UL * M2)
#define OFF_K   (3UL * M2)
#define OFF_V   (4UL * M2)
#define OFF_ATT (5UL * M2)
#define OFF_QI  (6UL * M2)
#define OFF_KI  (6UL * M2 + 524288UL)
#define OFF_IS  (7UL * M2)
#define OFF_Y   (8UL * M2)
#define OFF_HID (16UL * M2)

__device__ unsigned g_selmask[NT * 32];
__device__ int      g_elist[NE * NT];
__device__ int      g_ecount[NE];
__device__ int      g_tope[NT * 2];
__device__ float    g_gate[NT * 2];
__device__ int      g_slot[NT * 2];

// ---------------- helpers ----------------
__device__ __forceinline__ float gelu_f(float x) {
    const float c = 0.7978845608028654f;
    float x3 = x * x * x;
    return 0.5f * x * (1.0f + tanhf(c * (x + 0.044715f * x3)));
}

// ---------------- embedding ----------------
__global__ void embed_kernel(const int* __restrict__ ids,
                             const float* __restrict__ tok_emb,
                             const float* __restrict__ pos_emb,
                             float* __restrict__ h) {
    long idx = (long)blockIdx.x * blockDim.x + threadIdx.x;
    if (idx >= (long)NT * D) return;
    int tok = (int)(idx / D);
    int d   = (int)(idx % D);
    int s   = tok % S;
    h[idx] = tok_emb[(long)ids[tok] * D + d] + pos_emb[(long)s * D + d];
}

// ---------------- layernorm ----------------
__global__ void ln_kernel(const float* __restrict__ x,
                          const float* __restrict__ g,
                          const float* __restrict__ b,
                          float* __restrict__ y) {
    int row = blockIdx.x;
    int t = threadIdx.x;
    __shared__ float red[256];
    __shared__ float s_mean, s_inv;
    const float* xr = x + (long)row * D;
    float s = 0.f;
    for (int i = t; i < D; i += 256) s += xr[i];
    red[t] = s; __syncthreads();
    for (int o = 128; o > 0; o >>= 1) { if (t < o) red[t] += red[t + o]; __syncthreads(); }
    if (t == 0) s_mean = red[0] / (float)D;
    __syncthreads();
    float m = s_mean;
    float s2 = 0.f;
    for (int i = t; i < D; i += 256) { float d = xr[i] - m; s2 += d * d; }
    red[t] = s2; __syncthreads();
    for (int o = 128; o > 0; o >>= 1) { if (t < o) red[t] += red[t + o]; __syncthreads(); }
    if (t == 0) s_inv = rsqrtf(red[0] / (float)D + EPS);
    __syncthreads();
    float inv = s_inv;
    float* yr = y + (long)row * D;
    for (int i = t; i < D; i += 256) yr[i] = (xr[i] - m) * inv * g[i] + b[i];
}

// ---------------- Kahan scalar GEMM for indexer projections ----------------
// C[N,M] = A[N,K] @ W[K,M] + bias. Compensated accumulation: error ~2^-24 rel
// (kills my side of the relu-sign flip window). 64x64 tile, BK=16, 256 thr.
__global__ __launch_bounds__(256)
void sgemm_kahan_kernel(const float* __restrict__ A, const float* __restrict__ W,
                        const float* __restrict__ bias, float* __restrict__ C,
                        int N, int M, int K) {
    int br = blockIdx.y * 64;
    int bc = blockIdx.x * 64;

    __shared__ float As[16][64];
    __shared__ float Bs[16][64];

    int t = threadIdx.x;
    int tx = t & 15, ty = t >> 4;

    int ar = t >> 2;
    int ac4 = (t & 3) * 4;
    int bk = t >> 4;
    int bc4 = (t & 15) * 4;

    float acc[4][4], cmp[4][4];
#pragma unroll
    for (int i = 0; i < 4; i++)
#pragma unroll
        for (int j = 0; j < 4; j++) { acc[i][j] = 0.f; cmp[i][j] = 0.f; }

    for (int k0 = 0; k0 < K; k0 += 16) {
        float4 av = *(const float4*)&A[(long)(br + ar) * K + k0 + ac4];
        As[ac4 + 0][ar] = av.x;
        As[ac4 + 1][ar] = av.y;
        As[ac4 + 2][ar] = av.z;
        As[ac4 + 3][ar] = av.w;
        *(float4*)&Bs[bk][bc4] = *(const float4*)&W[(long)(k0 + bk) * M + bc + bc4];
        __syncthreads();
#pragma unroll
        for (int kk = 0; kk < 16; kk++) {
            float a[4], b[4];
#pragma unroll
            for (int i = 0; i < 4; i++) a[i] = As[kk][ty * 4 + i];
#pragma unroll
            for (int j = 0; j < 4; j++) b[j] = Bs[kk][tx * 4 + j];
#pragma unroll
            for (int i = 0; i < 4; i++)
#pragma unroll
                for (int j = 0; j < 4; j++) {
                    float p = a[i] * b[j];
                    float y = p - cmp[i][j];
                    float tt = acc[i][j] + y;
                    cmp[i][j] = (tt - acc[i][j]) - y;
                    acc[i][j] = tt;
                }
        }
        __syncthreads();
    }

#pragma unroll
    for (int i = 0; i < 4; i++) {
        int row = br + ty * 4 + i;
#pragma unroll
        for (int j = 0; j < 4; j++) {
            int col = bc + tx * 4 + j;
            C[(long)row * M + col] = acc[i][j] + bias[col];
        }
    }
}

// ---------------- 6-term BF16 tensor-core GEMM ----------------
// C[N,M] = act(A[N,K] @ W[K,M] + bias) (+resid). fp32 in/out, fp32-par via
// 3-way bf16 split; TERMS=6: hh+mh+hm+mm+lh+hl (residual ~1.2e-7),
// TERMS=4: hh+mh+hm+mm (residual ~1.5e-5, logits only).
// 128x128 tile, BK=16 (one m16n8k16 k-step), 8 warps (2x4), warp tile 64x32.
// smem planes bf16 [row][k] pitch 20 b16 (=10 uints), double buffered.
#define U_AH 0
#define U_AM 1280
#define U_AL 2560
#define U_BH 3840
#define U_BM 5120
#define U_BL 6400
#define U_BUF 7680
#define GEMM_SMEM_B (2 * U_BUF * 4)

#define MMA_BF16(c, a, b) \
  asm volatile("mma.sync.aligned.m16n8k16.row.col.f32.bf16.bf16.f32 " \
      "{%0,%1,%2,%3}, {%4,%5,%6,%7}, {%8,%9}, {%0,%1,%2,%3};" \
      : "+f"((c)[0]), "+f"((c)[1]), "+f"((c)[2]), "+f"((c)[3]) \
      : "r"((a)[0]), "r"((a)[1]), "r"((a)[2]), "r"((a)[3]), \
        "r"((b)[0]), "r"((b)[1]))

__device__ __forceinline__ void split_pack(float x0, float x1,
                                           unsigned& ph, unsigned& pm, unsigned& pl,
                                           bool need_l) {
    __nv_bfloat16 h0 = __float2bfloat16_rn(x0);
    __nv_bfloat16 h1 = __float2bfloat16_rn(x1);
    float r0 = x0 - __bfloat162float(h0);
    float r1 = x1 - __bfloat162float(h1);
    __nv_bfloat16 m0 = __float2bfloat16_rn(r0);
    __nv_bfloat16 m1 = __float2bfloat16_rn(r1);
    __nv_bfloat162 hp; hp.x = h0; hp.y = h1;
    __nv_bfloat162 mp; mp.x = m0; mp.y = m1;
    ph = *(unsigned*)&hp;
    pm = *(unsigned*)&mp;
    if (need_l) {
        float s0 = r0 - __bfloat162float(m0);
        float s1 = r1 - __bfloat162float(m1);
        __nv_bfloat162 lp; lp.x = __float2bfloat16_rn(s0); lp.y = __float2bfloat16_rn(s1);
        pl = *(unsigned*)&lp;
    }
}

template<int TERMS>
__global__ __launch_bounds__(256, 2)
void gemm_bf16_kernel(const float* __restrict__ A, const float* __restrict__ W,
                      const float* __restrict__ bias, const float* __restrict__ resid,
                      float* __restrict__ C, int N, int M, int K,
                      const int* __restrict__ row_idx, const int* __restrict__ n_ptr,
                      int act) {
    extern __shared__ unsigned usm[];
    int n = n_ptr ? *n_ptr : N;
    int br = blockIdx.y * 128;
    int bc = blockIdx.x * 128;
    if (br >= n) return;

    int t = threadIdx.x;
    int warp = t >> 5, lane = t & 31;
    int wm = (warp >> 2) * 64;
    int wn = (warp & 3) * 32;
    int g = lane >> 2, cc = lane & 3;

    // A staging: thread owns (row = t>>1, k = (t&1)*8 .. +7)
    int am_row = t >> 1;
    int am_k8  = (t & 1) * 8;
    long arow;
    {
        int gr = br + am_row;
        arow = (gr < n) ? (row_idx ? (long)row_idx[gr] : (long)gr) : 0;
    }
    // B staging: thread owns (n-col = t&127, k = (t>>7)*8 .. +7)
    int bn  = t & 127;
    int bk8 = (t >> 7) * 8;

    float acc[4][4][4];
#pragma unroll
    for (int i = 0; i < 4; i++)
#pragma unroll
        for (int j = 0; j < 4; j++)
#pragma unroll
            for (int c = 0; c < 4; c++) acc[i][j][c] = 0.f;

    float aS[8], bS[8];

    auto loadG = [&](int k0) {
        float4 x = *(const float4*)(A + arow * K + k0 + am_k8);
        float4 y = *(const float4*)(A + arow * K + k0 + am_k8 + 4);
        aS[0] = x.x; aS[1] = x.y; aS[2] = x.z; aS[3] = x.w;
        aS[4] = y.x; aS[5] = y.y; aS[6] = y.z; aS[7] = y.w;
#pragma unroll
        for (int j = 0; j < 8; j++)
            bS[j] = W[(long)(k0 + bk8 + j) * M + bc + bn];
    };

    auto storeS = [&](int bufi) {
        unsigned* base = usm + bufi * U_BUF;
        int ua = am_row * 10 + (am_k8 >> 1);
#pragma unroll
        for (int j = 0; j < 4; j++) {
            unsigned ph, pm, pl = 0;
            split_pack(aS[2 * j], aS[2 * j + 1], ph, pm, pl, TERMS == 6);
            base[U_AH + ua + j] = ph;
            base[U_AM + ua + j] = pm;
            if (TERMS == 6) base[U_AL + ua + j] = pl;
        }
        int ub = bn * 10 + (bk8 >> 1);
#pragma unroll
        for (int j = 0; j < 4; j++) {
            unsigned ph, pm, pl = 0;
            split_pack(bS[2 * j], bS[2 * j + 1], ph, pm, pl, TERMS == 6);
            base[U_BH + ub + j] = ph;
            base[U_BM + ub + j] = pm;
            if (TERMS == 6) base[U_BL + ub + j] = pl;
        }
    };

    auto compute = [&](int bufi) {
        const unsigned* base = usm + bufi * U_BUF;
#pragma unroll
        for (int mt = 0; mt < 4; mt++) {
            int o = (wm + mt * 16 + g) * 10 + cc;
            unsigned ah[4] = {base[U_AH + o], base[U_AH + o + 80],
                              base[U_AH + o + 4], base[U_AH + o + 84]};
            unsigned am[4] = {base[U_AM + o], base[U_AM + o + 80],
                              base[U_AM + o + 4], base[U_AM + o + 84]};
            unsigned al[4] = {0u, 0u, 0u, 0u};
            if (TERMS == 6) {
                al[0] = base[U_AL + o];      al[1] = base[U_AL + o + 80];
                al[2] = base[U_AL + o + 4];  al[3] = base[U_AL + o + 84];
            }
#pragma unroll
            for (int nt = 0; nt < 4; nt++) {
                int q = (wn + nt * 8 + g) * 10 + cc;
                unsigned bh[2] = {base[U_BH + q], base[U_BH + q + 4]};
                unsigned bm[2] = {base[U_BM + q], base[U_BM + q + 4]};
                MMA_BF16(acc[mt][nt], ah, bh);
                MMA_BF16(acc[mt][nt], am, bh);
                MMA_BF16(acc[mt][nt], ah, bm);
                MMA_BF16(acc[mt][nt], am, bm);
                if (TERMS == 6) {
                    unsigned bl[2] = {base[U_BL + q], base[U_BL + q + 4]};
                    MMA_BF16(acc[mt][nt], al, bh);
                    MMA_BF16(acc[mt][nt], ah, bl);
                }
            }
        }
    };

    int NI = K / 16;
    loadG(0);
    storeS(0);
    __syncthreads();
    for (int it = 0; it < NI; it++) {
        if (it + 1 < NI) loadG((it + 1) * 16);
        compute(it & 1);
        if (it + 1 < NI) storeS((it + 1) & 1);
        __syncthreads();
    }

#pragma unroll
    for (int mt = 0; mt < 4; mt++) {
        int r0 = br + wm + mt * 16 + g;
        int r1 = r0 + 8;
#pragma unroll
        for (int nt = 0; nt < 4; nt++) {
            int c = bc + wn + nt * 8 + cc * 2;
            float v00 = acc[mt][nt][0], v01 = acc[mt][nt][1];
            float v10 = acc[mt][nt][2], v11 = acc[mt][nt][3];
            if (bias) {
                float b0 = bias[c], b1 = bias[c + 1];
                v00 += b0; v01 += b1; v10 += b0; v11 += b1;
            }
            if (act == 1) {
                v00 = gelu_f(v00); v01 = gelu_f(v01);
                v10 = gelu_f(v10); v11 = gelu_f(v11);
            }
            if (r0 < n) {
                long o = (long)r0 * M + c;
                if (resid) { v00 += resid[o]; v01 += resid[o + 1]; }
                C[o] = v00; C[o + 1] = v01;
            }
            if (r1 < n) {
                long o = (long)r1 * M + c;
                if (resid) { v10 += resid[o]; v11 += resid[o + 1]; }
                C[o] = v10; C[o + 1] = v11;
            }
        }
    }
}

// ---------------- indexer scores (Kahan dots) ----------------
__global__ void idx_score_kernel(const float* __restrict__ qi,
                                 const float* __restrict__ ki,
                                 const float* __restrict__ hw,
                                 float* __restrict__ sc) {
    int row = blockIdx.x;
    int b = row / S;
    int t = threadIdx.x;
    __shared__ float qs[IHD];
    __shared__ float w[IH];
    if (t < IHD) qs[t] = qi[(long)row * IHD + t];
    if (t < IH) w[t] = hw[t];
    __syncthreads();
    for (int k = t; k < S; k += 256) {
        const float* kr = ki + (long)(b * S + k) * IHD;
        float s = 0.f;
#pragma unroll
        for (int hh = 0; hh < IH; hh++) {
            float d = 0.f, cmp = 0.f;
#pragma unroll
            for (int i = 0; i < ID; i++) {
                float p = qs[hh * ID + i] * kr[hh * ID + i];
                float y = p - cmp;
                float tt = d + y;
                cmp = (tt - d) - y;
                d = tt;
            }
            s += w[hh] * fmaxf(d, 0.f);
        }
        sc[(long)row * S + k] = s;
    }
}

// ---------------- exact stable top-k (rank counting) ----------------
__global__ void topk_kernel(const float* __restrict__ sc, unsigned* __restrict__ sel) {
    int row = blockIdx.x;
    int t = threadIdx.x;
    __shared__ float s[S];
    s[t] = sc[(long)row * S + t];
    __syncthreads();
    float v = s[t];
    int cnt = 0;
    for (int i = 0; i < S; i++) {
        float si = s[i];
        cnt += (si > v) || (si == v && i < t);
    }
    unsigned ball = __ballot_sync(0xffffffffu, cnt < KSEL);
    if ((t & 31) == 0) sel[row * 32 + (t >> 5)] = ball;
}

// ---------------- fused attention ----------------
__global__ void attn_kernel(const float* __restrict__ q, const float* __restrict__ k,
                            const float* __restrict__ v, const unsigned* __restrict__ selmask,
                            float* __restrict__ out) {
    int idx = blockIdx.x;
    int qpos = idx % S;
    int hh = (idx / S) % H;
    int b = idx / (S * H);
    int t = threadIdx.x;

    __shared__ float qs[DH];
    __shared__ float sc[S];
    __shared__ float red[256];
    __shared__ float s_max, s_inv;

    const float* qrow = q + ((long)(b * S + qpos) * D + hh * DH);
    if (t < DH) qs[t] = qrow[t];
    __syncthreads();

    const unsigned* selrow = selmask + (long)(b * S + qpos) * 32;
    for (int kk = t; kk < S; kk += 256) {
        const float* krow = k + ((long)(b * S + kk) * D + hh * DH);
        float d = 0.f;
#pragma unroll
        for (int i = 0; i < DH; i++) d += qs[i] * krow[i];
        d *= 0.125f;
        bool allowed = (kk <= qpos) && ((selrow[kk >> 5] >> (kk & 31)) & 1u);
        sc[kk] = allowed ? d : (d + NEGV);
    }
    __syncthreads();

    float m = -INFINITY;
    for (int kk = t; kk < S; kk += 256) m = fmaxf(m, sc[kk]);
    red[t] = m; __syncthreads();
    for (int o = 128; o > 0; o >>= 1) { if (t < o) red[t] = fmaxf(red[t], red[t + o]); __syncthreads(); }
    if (t == 0) s_max = red[0];
    __syncthreads();
    float mx = s_max;

    float sum = 0.f;
    for (int kk = t; kk < S; kk += 256) {
        float p = expf(sc[kk] - mx);
        sc[kk] = p;
        sum += p;
    }
    red[t] = sum; __syncthreads();
    for (int o = 128; o > 0; o >>= 1) { if (t < o) red[t] += red[t + o]; __syncthreads(); }
    if (t == 0) s_inv = 1.f / red[0];
    __syncthreads();
    float inv = s_inv;

    int d = t & 63;
    int chunk = t >> 6;
    float acc = 0.f;
    int kbeg = chunk * 256, kend = kbeg + 256;
    for (int kk = kbeg; kk < kend; kk++)
        acc += sc[kk] * v[(long)(b * S + kk) * D + hh * DH + d];
    red[t] = acc; __syncthreads();
    if (t < 64) {
        float o = (red[t] + red[t + 64] + red[t + 128] + red[t + 192]) * inv;
        out[(long)(b * S + qpos) * D + hh * DH + t] = o;
    }
}

// ---------------- router ----------------
__global__ void router_kernel(const float* __restrict__ x, const float* __restrict__ w,
                              const float* __restrict__ bias,
                              int* __restrict__ tope, float* __restrict__ gate,
                              int* __restrict__ slot, int* __restrict__ elist,
                              int* __restrict__ ecount) {
    int tkn = blockIdx.x;
    int t = threadIdx.x;
    int e = t >> 5, lane = t & 31;
    __shared__ float logit[NE];
    const float* xr = x + (long)tkn * D;
    float s = 0.f;
    for (int i = lane; i < D; i += 32) s += xr[i] * w[(long)i * NE + e];
#pragma unroll
    for (int o = 16; o > 0; o >>= 1) s += __shfl_down_sync(0xffffffffu, s, o);
    if (lane == 0) logit[e] = s + bias[e];
    __syncthreads();
    if (t == 0) {
        float mx = logit[0];
        for (int i = 1; i < NE; i++) mx = fmaxf(mx, logit[i]);
        float p[NE]; float sum = 0.f;
        for (int i = 0; i < NE; i++) { p[i] = expf(logit[i] - mx); sum += p[i]; }
        float invs = 1.f / sum;
        for (int i = 0; i < NE; i++) p[i] *= invs;
        int i0 = 0;
        for (int i = 1; i < NE; i++) if (p[i] > p[i0]) i0 = i;
        int i1 = -1;
        for (int i = 0; i < NE; i++) { if (i == i0) continue; if (i1 < 0 || p[i] > p[i1]) i1 = i; }
        float g0 = p[i0], g1 = p[i1];
        float ginv = 1.f / (g0 + g1);
        g0 *= ginv; g1 *= ginv;
        tope[2 * tkn] = i0; tope[2 * tkn + 1] = i1;
        gate[2 * tkn] = g0; gate[2 * tkn + 1] = g1;
        int s0 = atomicAdd(&ecount[i0], 1); elist[i0 * NT + s0] = tkn; slot[2 * tkn] = s0;
        int s1 = atomicAdd(&ecount[i1], 1); elist[i1 * NT + s1] = tkn; slot[2 * tkn + 1] = s1;
    }
}

__global__ void zero_counts_kernel(int* __restrict__ ecount) {
    if (threadIdx.x < NE) ecount[threadIdx.x] = 0;
}

// ---------------- MoE gather ----------------
__global__ void moe_gather_kernel(const float* __restrict__ y, const int* __restrict__ tope,
                                  const float* __restrict__ gate, const int* __restrict__ slot,
                                  float* __restrict__ h) {
    long idx = (long)blockIdx.x * blockDim.x + threadIdx.x;
    if (idx >= (long)NT * D) return;
    int tkn = (int)(idx / D);
    int d = (int)(idx % D);
    int e0 = tope[2 * tkn], e1 = tope[2 * tkn + 1];
    float g0 = gate[2 * tkn], g1 = gate[2 * tkn + 1];
    long r0 = (long)(e0 * NT + slot[2 * tkn]) * D + d;
    long r1 = (long)(e1 * NT + slot[2 * tkn + 1]) * D + d;
    h[idx] += g0 * y[r0] + g1 * y[r1];
}

// ---------------- launch ----------------
static inline void launch_gemm6(const float* A, const float* W, const float* bias,
                                const float* resid, float* C, int N, int M, int K,
                                const int* row_idx, const int* n_ptr, int act) {
    dim3 grid((M + 127) / 128, (N + 127) / 128);
    gemm_bf16_kernel<6><<<grid, 256, GEMM_SMEM_B>>>(A, W, bias, resid, C, N, M, K, row_idx, n_ptr, act);
}
static inline void launch_gemm4(const float* A, const float* W, const float* bias,
                                const float* resid, float* C, int N, int M, int K,
                                const int* row_idx, const int* n_ptr, int act) {
    dim3 grid((M + 127) / 128, (N + 127) / 128);
    gemm_bf16_kernel<4><<<grid, 256, GEMM_SMEM_B>>>(A, W, bias, resid, C, N, M, K, row_idx, n_ptr, act);
}

extern "C" void kernel_launch(void* const* d_in, const int* in_sizes, int n_in,
                              void* d_out, int out_size) {
    const int*   input_ids = (const int*)d_in[0];
    const float* tok_emb   = (const float*)d_in[1];
    const float* pos_emb   = (const float*)d_in[2];
    const float* ind_qw    = (const float*)d_in[3];
    const float* ind_qb    = (const float*)d_in[4];
    const float* ind_kw    = (const float*)d_in[5];
    const float* ind_kb    = (const float*)d_in[6];
    const float* ind_hw    = (const float*)d_in[7];
    const float* an_g      = (const float*)d_in[8];
    const float* an_b      = (const float*)d_in[9];
    const float* q_w       = (const float*)d_in[10];
    const float* q_b       = (const float*)d_in[11];
    const float* k_w       = (const float*)d_in[12];
    const float* k_b       = (const float*)d_in[13];
    const float* v_w       = (const float*)d_in[14];
    const float* v_b       = (const float*)d_in[15];
    const float* o_w       = (const float*)d_in[16];
    const float* o_b       = (const float*)d_in[17];
    const float* mn_g      = (const float*)d_in[18];
    const float* mn_b      = (const float*)d_in[19];
    const float* router_w  = (const float*)d_in[20];
    const float* router_b  = (const float*)d_in[21];
    const float* e_w1      = (const float*)d_in[22];
    const float* e_b1      = (const float*)d_in[23];
    const float* e_w2      = (const float*)d_in[24];
    const float* e_b2      = (const float*)d_in[25];
    const float* ln_g      = (const float*)d_in[26];
    const float* ln_b      = (const float*)d_in[27];
    const float* out_w     = (const float*)d_in[28];
    const float* out_b     = (const float*)d_in[29];
    float* out = (float*)d_out;

    cudaFuncSetAttribute(gemm_bf16_kernel<6>, cudaFuncAttributeMaxDynamicSharedMemorySize, GEMM_SMEM_B);
    cudaFuncSetAttribute(gemm_bf16_kernel<4>, cudaFuncAttributeMaxDynamicSharedMemorySize, GEMM_SMEM_B);

    float* buf = nullptr;
    cudaGetSymbolAddress((void**)&buf, g_buf);
    unsigned* selmask = nullptr; cudaGetSymbolAddress((void**)&selmask, g_selmask);
    int* elist = nullptr;  cudaGetSymbolAddress((void**)&elist, g_elist);
    int* ecount = nullptr; cudaGetSymbolAddress((void**)&ecount, g_ecount);
    int* tope = nullptr;   cudaGetSymbolAddress((void**)&tope, g_tope);
    float* gate = nullptr; cudaGetSymbolAddress((void**)&gate, g_gate);
    int* slot = nullptr;   cudaGetSymbolAddress((void**)&slot, g_slot);

    float* h    = buf + OFF_H;
    float* hn   = buf + OFF_HN;
    float* qb   = buf + OFF_Q;
    float* kb   = buf + OFF_K;
    float* vb   = buf + OFF_V;
    float* attb = buf + OFF_ATT;
    float* qib  = buf + OFF_QI;
    float* kib  = buf + OFF_KI;
    float* isb  = buf + OFF_IS;
    float* yb   = buf + OFF_Y;
    float* hidb = buf + OFF_HID;

    embed_kernel<<<(NT * D + 255) / 256, 256>>>(input_ids, tok_emb, pos_emb, h);

    for (int l = 0; l < LAYERS; l++) {
        const float* iqw = ind_qw + (long)l * D * IHD;
        const float* iqb_ = ind_qb + (long)l * IHD;
        const float* ikw = ind_kw + (long)l * D * IHD;
        const float* ikb_ = ind_kb + (long)l * IHD;
        const float* ihw = ind_hw + (long)l * IH;

        // indexer path: compensated scalar (decision-critical)
        sgemm_kahan_kernel<<<dim3(IHD / 64, NT / 64), 256>>>(h, iqw, iqb_, qib, NT, IHD, D);
        sgemm_kahan_kernel<<<dim3(IHD / 64, NT / 64), 256>>>(h, ikw, ikb_, kib, NT, IHD, D);
        idx_score_kernel<<<NT, 256>>>(qib, kib, ihw, isb);
        topk_kernel<<<NT, 1024>>>(isb, selmask);

        ln_kernel<<<NT, 256>>>(h, an_g + (long)l * D, an_b + (long)l * D, hn);
        launch_gemm6(hn, q_w + (long)l * D * D, q_b + (long)l * D, nullptr, qb, NT, D, D, nullptr, nullptr, 0);
        launch_gemm6(hn, k_w + (long)l * D * D, k_b + (long)l * D, nullptr, kb, NT, D, D, nullptr, nullptr, 0);
        launch_gemm6(hn, v_w + (long)l * D * D, v_b + (long)l * D, nullptr, vb, NT, D, D, nullptr, nullptr, 0);
        attn_kernel<<<B * H * S, 256>>>(qb, kb, vb, selmask, attb);
        launch_gemm6(attb, o_w + (long)l * D * D, o_b + (long)l * D, h, h, NT, D, D, nullptr, nullptr, 0);

        ln_kernel<<<NT, 256>>>(h, mn_g + (long)l * D, mn_b + (long)l * D, hn);
        zero_counts_kernel<<<1, 32>>>(ecount);
        router_kernel<<<NT, 256>>>(hn, router_w + (long)l * D * NE, router_b + (long)l * NE,
                                   tope, gate, slot, elist, ecount);
        for (int e = 0; e < NE; e++) {
            const float* w1 = e_w1 + ((long)l * NE + e) * (long)D * FF;
            const float* b1 = e_b1 + ((long)l * NE + e) * FF;
            launch_gemm6(hn, w1, b1, nullptr, hidb + (long)e * NT * FF, NT, FF, D,
                         elist + e * NT, ecount + e, 1);
        }
        for (int e = 0; e < NE; e++) {
            const float* w2 = e_w2 + ((long)l * NE + e) * (long)FF * D;
            const float* b2 = e_b2 + ((long)l * NE + e) * D;
            launch_gemm6(hidb + (long)e * NT * FF, w2, b2, nullptr, yb + (long)e * NT * D,
                         NT, D, FF, nullptr, ecount + e, 0);
        }
        moe_gather_kernel<<<(NT * D + 255) / 256, 256>>>(yb, tope, gate, slot, h);
    }

    ln_kernel<<<NT, 256>>>(h, ln_g, ln_b, hn);
    launch_gemm4(hn, out_w, out_b, nullptr, out, NT, V, D, nullptr, nullptr, 0);
}